// round 11
// baseline (speedup 1.0000x reference)
#include <cuda_runtime.h>
#include <cstdint>

#define BSZ  4
#define CH   128
#define HID  256
#define OUTD 64
#define EPSV 1e-5f
#define ALLM 0xffffffffu
#define CLN  8                 // CTAs per cluster = chunks per level

__device__ __forceinline__ uint32_t smem_u32(const void* p)
{
    uint32_t a;
    asm("{ .reg .u64 t; cvta.to.shared.u64 t, %1; cvt.u32.u64 %0, t; }"
        : "=r"(a) : "l"(p));
    return a;
}

// ---------------------------------------------------------------------------
// 5 clusters of 8 CTAs (one cluster per level), 256 threads/CTA.
// Phase1: each CTA computes 32 hidden units; pushes its 128 r-values into ALL
// 8 cluster CTAs' smem via st.async + mbarrier complete_tx (4096 B expected).
// Phase2: local mbarrier wait (no L2 spin), r read from LOCAL smem.
// ---------------------------------------------------------------------------
__global__ void __cluster_dims__(CLN, 1, 1) __launch_bounds__(256, 1)
proj_fused_kernel(const float* __restrict__ x0,
                  const float* __restrict__ x1,
                  const float* __restrict__ x2,
                  const float* __restrict__ x3,
                  const float* __restrict__ x4,
                  const int*   __restrict__ p,
                  const float* __restrict__ w1,
                  const float* __restrict__ b1,
                  const float* __restrict__ gamma,
                  const float* __restrict__ beta,
                  const float* __restrict__ w2,
                  const float* __restrict__ b2,
                  float*       __restrict__ out)
{
    const int k   = blockIdx.x >> 3;       // level 0..4 (cluster id)
    const int ch8 = blockIdx.x & 7;        // rank within cluster
    const int t   = threadIdx.x;
    const int s   = t & 7;                 // interleaved float4 slot
    const int j   = ch8 * 32 + (t >> 3);   // hidden unit (phase1)

    __shared__ float f_s[BSZ][CH];
    __shared__ float r_all[BSZ * HID];     // full level's activations (pushed in)
    __shared__ alignas(8) unsigned long long mbar_s;

    const uint32_t mbar_a = smem_u32(&mbar_s);
    const uint32_t r_base = smem_u32(r_all);

    // ---- mbarrier init: 1 arrival (the expect_tx below), 4096 tx bytes ----
    if (t == 0) {
        asm volatile("mbarrier.init.shared.b64 [%0], 1;" :: "r"(mbar_a) : "memory");
        asm volatile("fence.mbarrier_init.release.cluster;" ::: "memory");
        asm volatile("mbarrier.arrive.expect_tx.shared.b64 _, [%0], %1;"
                     :: "r"(mbar_a), "r"(BSZ * HID * 4) : "memory");
    }
    __syncthreads();
    asm volatile("barrier.cluster.arrive.aligned;" ::: "memory");

    // ================= gather FIRST: the p -> x chain is the critical path ==
    const float* xs;
    switch (k) {
        case 0: xs = x0; break;
        case 1: xs = x1; break;
        case 2: xs = x2; break;
        case 3: xs = x3; break;
        default: xs = x4; break;
    }
    const int shift = k + 1;
    const int side  = 128 >> shift;

    {
        const int i0 = t;
        const int i1 = t + 256;
        const int ba = i0 >> 7, ca = i0 & (CH - 1);
        const int bb = i1 >> 7, cb = i1 & (CH - 1);
        const int qa0 = p[ba * 3 + 0] >> shift;
        const int qa1 = p[ba * 3 + 1] >> shift;
        const int qa2 = p[ba * 3 + 2] >> shift;
        const int qb0 = p[bb * 3 + 0] >> shift;
        const int qb1 = p[bb * 3 + 1] >> shift;
        const int qb2 = p[bb * 3 + 2] >> shift;
        const long long ia =
            ((((long long)(ba * CH + ca) * side + qa0) * side + qa1) * side + qa2);
        const long long ib =
            ((((long long)(bb * CH + cb) * side + qb0) * side + qb1) * side + qb2);
        f_s[ba][ca] = xs[ia];
        f_s[bb][cb] = xs[ib];
    }

    // ---- weight / BN / w2 prefetch: latency hidden under gather ----
    const float4* wrow = (const float4*)(w1 + ((long long)k * HID + j) * CH);
    float4 wv[4];
    #pragma unroll
    for (int i = 0; i < 4; ++i)
        wv[i] = wrow[s + 8 * i];

    const float bias = b1[k * HID + j];
    const float gam  = gamma[k * HID + j];
    const float bet  = beta[k * HID + j];

    const int T = t >> 3;                   // 0..31
    const int b = T & 3;
    const int o = ch8 * 8 + (T >> 2);
    const float4* w2row = (const float4*)(w2 + ((long long)k * OUTD + o) * HID);
    float4 wv2[8];
    #pragma unroll
    for (int i = 0; i < 8; ++i)
        wv2[i] = w2row[s + 8 * i];
    const float bias2 = b2[k * OUTD + o];

    // cluster wait overlaps the gather's memory latency
    asm volatile("barrier.cluster.wait.aligned;" ::: "memory");
    __syncthreads();

    // ================= PHASE 1: 16 ch x 4 batches per thread =================
    const float4* f0 = (const float4*)f_s[0];
    const float4* f1 = (const float4*)f_s[1];
    const float4* f2 = (const float4*)f_s[2];
    const float4* f3 = (const float4*)f_s[3];

    float a0 = 0.f, a1 = 0.f, a2 = 0.f, a3 = 0.f;
    #pragma unroll
    for (int i = 0; i < 4; ++i) {
        const int fi = s + 8 * i;
        const float4 w = wv[i];
        float4 v;
        v = f0[fi]; a0 += v.x*w.x + v.y*w.y + v.z*w.z + v.w*w.w;
        v = f1[fi]; a1 += v.x*w.x + v.y*w.y + v.z*w.z + v.w*w.w;
        v = f2[fi]; a2 += v.x*w.x + v.y*w.y + v.z*w.z + v.w*w.w;
        v = f3[fi]; a3 += v.x*w.x + v.y*w.y + v.z*w.z + v.w*w.w;
    }
    #pragma unroll
    for (int m = 1; m < 8; m <<= 1) {
        a0 += __shfl_xor_sync(ALLM, a0, m);
        a1 += __shfl_xor_sync(ALLM, a1, m);
        a2 += __shfl_xor_sync(ALLM, a2, m);
        a3 += __shfl_xor_sync(ALLM, a3, m);
    }

    a0 += bias; a1 += bias; a2 += bias; a3 += bias;
    const float mean = 0.25f * (a0 + a1 + a2 + a3);
    const float d0 = a0 - mean, d1 = a1 - mean, d2 = a2 - mean, d3 = a3 - mean;
    const float var = 0.25f * (d0*d0 + d1*d1 + d2*d2 + d3*d3);
    const float scl = gam * rsqrtf(var + EPSV);

    // ---- push r into ALL 8 cluster CTAs' smem (incl. self) via st.async ----
    if (s < 4) {
        const float d  = (s == 0) ? d0 : (s == 1) ? d1 : (s == 2) ? d2 : d3;
        const float rv = fmaxf(d * scl + bet, 0.f);
        const uint32_t roff = r_base + (uint32_t)(s * HID + j) * 4u;
        #pragma unroll
        for (int rk = 0; rk < CLN; ++rk) {
            asm volatile(
                "{\n\t"
                ".reg .u32 ra, rm;\n\t"
                "mapa.shared::cluster.u32 ra, %0, %2;\n\t"
                "mapa.shared::cluster.u32 rm, %1, %2;\n\t"
                "st.async.shared::cluster.mbarrier::complete_tx::bytes.f32 [ra], %3, [rm];\n\t"
                "}"
                :: "r"(roff), "r"(mbar_a), "r"(rk), "f"(rv) : "memory");
        }
    }

    // ---- wait: all 4096 bytes delivered into OUR smem (acquire) ----
    {
        uint32_t done;
        asm volatile(
            "{\n\t"
            ".reg .pred pd;\n\t"
            "mbarrier.try_wait.parity.acquire.cta.shared::cta.b64 pd, [%1], 0;\n\t"
            "selp.b32 %0, 1, 0, pd;\n\t"
            "}"
            : "=r"(done) : "r"(mbar_a) : "memory");
        if (!done) {
            asm volatile(
                "{\n\t"
                ".reg .pred pd;\n\t"
                "WL_%=:\n\t"
                "mbarrier.try_wait.parity.acquire.cta.shared::cta.b64 pd, [%0], 0, 0x989680;\n\t"
                "@pd bra.uni WD_%=;\n\t"
                "bra.uni WL_%=;\n\t"
                "WD_%=:\n\t"
                "}"
                :: "r"(mbar_a) : "memory");
        }
    }

    // ================= PHASE 2: 8 outs x 4 batches, r from LOCAL smem ========
    const float4* rrow = (const float4*)(r_all + b * HID);
    float acc = 0.f;
    #pragma unroll
    for (int i = 0; i < 8; ++i) {
        const float4 w = wv2[i];
        const float4 r = rrow[s + 8 * i];
        acc += r.x*w.x + r.y*w.y + r.z*w.z + r.w*w.w;
    }
    #pragma unroll
    for (int m = 1; m < 8; m <<= 1)
        acc += __shfl_xor_sync(ALLM, acc, m);

    if (s == 0)
        out[((long long)k * BSZ + b) * OUTD + o] = acc + bias2;
}

extern "C" void kernel_launch(void* const* d_in, const int* in_sizes, int n_in,
                              void* d_out, int out_size)
{
    (void)in_sizes; (void)n_in; (void)out_size;
    const float* x0    = (const float*)d_in[0];
    const float* x1    = (const float*)d_in[1];
    const float* x2    = (const float*)d_in[2];
    const float* x3    = (const float*)d_in[3];
    const float* x4    = (const float*)d_in[4];
    const int*   p     = (const int*)  d_in[5];
    const float* w1    = (const float*)d_in[6];
    const float* b1    = (const float*)d_in[7];
    const float* gamma = (const float*)d_in[8];
    const float* beta  = (const float*)d_in[9];
    const float* w2    = (const float*)d_in[10];
    const float* b2v   = (const float*)d_in[11];
    float* out = (float*)d_out;

    proj_fused_kernel<<<40, 256>>>(x0, x1, x2, x3, x4, p,
                                   w1, b1, gamma, beta, w2, b2v, out);
}